// round 15
// baseline (speedup 1.0000x reference)
#include <cuda_runtime.h>
#include <cuda_bf16.h>
#include <cstdint>

#define NN 50000
#define NE 800000
#define CH 128
#define NPAD 50048            // 391 * 128
#define MTILES 391
#define WROWS 2432            // W1(128) | W2(128) | heads(128) | Wa(2048)

// ---------------- scratch (no allocations allowed) ----------------
__device__ float g_dinv[NN];
__device__ int   g_cnt[NN];            // starts 0; k_scan re-zeroes after use
__device__ int   g_rowstart[NN + 1];
__device__ int   g_cursor[NN];
__device__ int   g_ecol[NE];
__device__ float g_enorm[NE];
__device__ float g_bufA[(size_t)NN * CH];
__device__ __nv_bfloat16 g_Xhi[(size_t)NPAD * CH];
__device__ __nv_bfloat16 g_Xlo[(size_t)NPAD * CH];
__device__ __nv_bfloat16 g_Whi[(size_t)WROWS * CH];
__device__ __nv_bfloat16 g_Wlo[(size_t)WROWS * CH];
__device__ float g_hbias[65];
__device__ int   g_is64;

// ================= helpers =================
__device__ __forceinline__ uint32_t smem_u32(const void* p) {
    uint32_t a;
    asm("{ .reg .u64 t; cvta.to.shared.u64 t, %1; cvt.u32.u64 %0, t; }" : "=r"(a) : "l"(p));
    return a;
}
__device__ __forceinline__ void ldmat_x4(uint32_t* r, uint32_t addr) {
    asm volatile("ldmatrix.sync.aligned.m8n8.x4.shared.b16 {%0,%1,%2,%3}, [%4];"
        : "=r"(r[0]), "=r"(r[1]), "=r"(r[2]), "=r"(r[3]) : "r"(addr));
}
__device__ __forceinline__ void mma16816(float* d, const uint32_t* a, const uint32_t* b) {
    asm volatile("mma.sync.aligned.m16n8k16.row.col.f32.bf16.bf16.f32 "
        "{%0,%1,%2,%3}, {%4,%5,%6,%7}, {%8,%9}, {%0,%1,%2,%3};"
        : "+f"(d[0]), "+f"(d[1]), "+f"(d[2]), "+f"(d[3])
        : "r"(a[0]), "r"(a[1]), "r"(a[2]), "r"(a[3]), "r"(b[0]), "r"(b[1]));
}
__device__ __forceinline__ void split_store(float v, __nv_bfloat16* hi, __nv_bfloat16* lo) {
    __nv_bfloat16 h = __float2bfloat16(v);
    *hi = h;
    *lo = __float2bfloat16(v - __bfloat162float(h));
}

// ---------------- edge-index dtype sniff ----------------
__global__ void k_detect(const int* __restrict__ ei32) {
    int z = 0;
    for (int i = 1; i < 256; i += 2)
        if (ei32[i] == 0) z++;
    g_is64 = (z > 64) ? 1 : 0;
}
__device__ __forceinline__ int edge_at(const void* __restrict__ ei, int pos) {
    if (g_is64) return (int)((const long long*)ei)[pos];
    return ((const int*)ei)[pos];
}

// ---------------- fused prep: feat split | weight split | degree count | bias pack ----
__global__ void k_prep(const float* __restrict__ x,
                       const float* __restrict__ W1, const float* __restrict__ W2,
                       const float* __restrict__ Wt, const float* __restrict__ Ws,
                       const float* __restrict__ Wf, const float* __restrict__ Wa,
                       const float* __restrict__ bt, const float* __restrict__ bs,
                       const float* __restrict__ bf, const void* __restrict__ ei) {
    int id = blockIdx.x * blockDim.x + threadIdx.x;

    // --- task 1: feature fp32 -> bf16 hi/lo (incl. zero pad rows) ---
    if (id < NPAD * CH / 4) {
        int row = id >> 5;
        float4 v = make_float4(0.f, 0.f, 0.f, 0.f);
        if (row < NN) v = ((const float4*)x)[id];
        __nv_bfloat16 h0 = __float2bfloat16(v.x), h1 = __float2bfloat16(v.y);
        __nv_bfloat16 h2 = __float2bfloat16(v.z), h3 = __float2bfloat16(v.w);
        __nv_bfloat162 hA(h0, h1), hB(h2, h3);
        __nv_bfloat162 lA(__float2bfloat16(v.x - __bfloat162float(h0)),
                          __float2bfloat16(v.y - __bfloat162float(h1)));
        __nv_bfloat162 lB(__float2bfloat16(v.z - __bfloat162float(h2)),
                          __float2bfloat16(v.w - __bfloat162float(h3)));
        ((__nv_bfloat162*)g_Xhi)[id * 2] = hA;
        ((__nv_bfloat162*)g_Xhi)[id * 2 + 1] = hB;
        ((__nv_bfloat162*)g_Xlo)[id * 2] = lA;
        ((__nv_bfloat162*)g_Xlo)[id * 2 + 1] = lB;
    }

    // --- task 2: all weights -> transposed [WROWS x 128] hi/lo ---
    if (id < WROWS * CH) {
        int n = id >> 7, k = id & 127;
        float v = 0.f;
        if (n < 128)       v = W1[(size_t)k * 128 + n];
        else if (n < 256)  v = W2[(size_t)k * 128 + (n - 128)];
        else if (n < 384) {
            int m = n - 256;
            if (m < 30)      v = Wt[(size_t)k * 30 + m];
            else if (m < 50) v = Ws[(size_t)k * 20 + (m - 30)];
            else if (m < 65) v = Wf[(size_t)k * 15 + (m - 50)];
        } else {
            int m = n - 384;
            if (m < 2000) v = Wa[(size_t)k * 2000 + m];
        }
        split_store(v, &g_Whi[id], &g_Wlo[id]);
    }

    // --- task 3: degree count ---
    if (id < NE) atomicAdd(&g_cnt[edge_at(ei, id)], 1);

    // --- task 4: packed small-head bias ---
    if (id < 30)      g_hbias[id] = bt[id];
    else if (id < 50) g_hbias[id] = bs[id - 30];
    else if (id < 65) g_hbias[id] = bf[id - 50];
}

// ---------------- scan (+dinv, +cnt clear) ----------------
__global__ void k_scan() {
    __shared__ int swarp[32];
    __shared__ int s_carry;
    int tid = threadIdx.x, lane = tid & 31, wid = tid >> 5;
    if (tid == 0) s_carry = 0;
    __syncthreads();
    for (int base = 0; base < NN; base += 1024) {
        int i = base + tid;
        int v = 0;
        if (i < NN) {
            v = g_cnt[i];
            g_dinv[i] = rsqrtf((float)(v + 1));
            g_cnt[i] = 0;
        }
        int incl = v;
        #pragma unroll
        for (int d = 1; d < 32; d <<= 1) {
            int n = __shfl_up_sync(0xffffffffu, incl, d);
            if (lane >= d) incl += n;
        }
        if (lane == 31) swarp[wid] = incl;
        __syncthreads();
        if (wid == 0) {
            int wv = swarp[lane];
            int wincl = wv;
            #pragma unroll
            for (int d = 1; d < 32; d <<= 1) {
                int n = __shfl_up_sync(0xffffffffu, wincl, d);
                if (lane >= d) wincl += n;
            }
            swarp[lane] = wincl - wv;
        }
        __syncthreads();
        int excl = s_carry + swarp[wid] + incl - v;
        if (i < NN) { g_rowstart[i] = excl; g_cursor[i] = excl; }
        __syncthreads();
        if (tid == 1023) s_carry = excl + v;
        __syncthreads();
    }
    if (threadIdx.x == 0) g_rowstart[NN] = s_carry;
}

__global__ void k_fill(const void* __restrict__ ei) {
    int e = blockIdx.x * blockDim.x + threadIdx.x;
    if (e >= NE) return;
    int r = edge_at(ei, e);
    int c = edge_at(ei, NE + e);
    int pos = atomicAdd(&g_cursor[r], 1);
    g_ecol[pos] = c;
    g_enorm[pos] = g_dinv[r] * g_dinv[c];
}

// ---------------- CSR gather aggregation (fused: self + bias + relu + bf16 split) ----
__global__ __launch_bounds__(256) void k_agg_csr(const float* __restrict__ hin,
                                                 const float* __restrict__ bias, int relu) {
    int node = blockIdx.x * 8 + (threadIdx.x >> 5);
    if (node >= NN) return;
    int lane = threadIdx.x & 31;
    float d = g_dinv[node];
    float dd = d * d;
    float4 acc = ((const float4*)(hin + (size_t)node * CH))[lane];
    acc.x *= dd; acc.y *= dd; acc.z *= dd; acc.w *= dd;

    int s = g_rowstart[node], e = g_rowstart[node + 1];
    int j = s;
    for (; j + 8 <= e; j += 8) {
        int   cc[8];
        float ww[8];
        #pragma unroll
        for (int q = 0; q < 8; ++q) { cc[q] = g_ecol[j + q]; ww[q] = g_enorm[j + q]; }
        float4 vv[8];
        #pragma unroll
        for (int q = 0; q < 8; ++q)
            vv[q] = ((const float4*)(hin + (size_t)cc[q] * CH))[lane];
        #pragma unroll
        for (int q = 0; q < 8; ++q) {
            acc.x += vv[q].x * ww[q];
            acc.y += vv[q].y * ww[q];
            acc.z += vv[q].z * ww[q];
            acc.w += vv[q].w * ww[q];
        }
    }
    for (; j < e; ++j) {
        int c0 = g_ecol[j];
        float w0 = g_enorm[j];
        float4 v0 = ((const float4*)(hin + (size_t)c0 * CH))[lane];
        acc.x += v0.x * w0; acc.y += v0.y * w0;
        acc.z += v0.z * w0; acc.w += v0.w * w0;
    }

    float4 b = ((const float4*)bias)[lane];
    acc.x += b.x; acc.y += b.y; acc.z += b.z; acc.w += b.w;
    if (relu) {
        acc.x = fmaxf(acc.x, 0.f); acc.y = fmaxf(acc.y, 0.f);
        acc.z = fmaxf(acc.z, 0.f); acc.w = fmaxf(acc.w, 0.f);
    }
    __nv_bfloat16 h0 = __float2bfloat16(acc.x), h1 = __float2bfloat16(acc.y);
    __nv_bfloat16 h2 = __float2bfloat16(acc.z), h3 = __float2bfloat16(acc.w);
    __nv_bfloat162 hA(h0, h1), hB(h2, h3);
    __nv_bfloat162 lA(__float2bfloat16(acc.x - __bfloat162float(h0)),
                      __float2bfloat16(acc.y - __bfloat162float(h1)));
    __nv_bfloat162 lB(__float2bfloat16(acc.z - __bfloat162float(h2)),
                      __float2bfloat16(acc.w - __bfloat162float(h3)));
    size_t o = (size_t)node * 64 + lane * 2;
    ((__nv_bfloat162*)g_Xhi)[o]     = hA;
    ((__nv_bfloat162*)g_Xhi)[o + 1] = hB;
    ((__nv_bfloat162*)g_Xlo)[o]     = lA;
    ((__nv_bfloat162*)g_Xlo)[o + 1] = lB;
}

// ---------------- mma.sync bf16-split GEMM (Round-13 config: occ 2) ----------------
// C[M x P] = A[M x 128] @ W[128 x P] (+bias), A/W pre-split into bf16 hi/lo.
// BM=128, BN=64, K=128 fully staged. 256 threads = 8 warps, warp tile 32x32.
#define SM_AH 0
#define SM_AL 32768
#define SM_BH 65536
#define SM_BL (65536 + 16384)
#define SM_TOTAL (65536 + 32768)

__device__ __forceinline__ uint32_t tile_off(int row, int chunk) {
    return (uint32_t)row * 256u + (uint32_t)((chunk ^ (row & 7)) << 4);
}

__global__ __launch_bounds__(256, 2) void k_mma_gemm(
    const __nv_bfloat16* __restrict__ Ah, const __nv_bfloat16* __restrict__ Al,
    const __nv_bfloat16* __restrict__ Bh, const __nv_bfloat16* __restrict__ Bl,
    const float* __restrict__ bias, float* __restrict__ C,
    int M, int P, int ntPerY, int mode,
    float* __restrict__ o1, float* __restrict__ o2, float* __restrict__ o3)
{
    extern __shared__ __align__(1024) char smem[];
    uint32_t sb = smem_u32(smem);
    int tid = threadIdx.x;
    int lane = tid & 31;
    int wid = tid >> 5;
    int wm = wid & 3;
    int wn = wid >> 2;
    int g = lane >> 3, i8 = lane & 7;
    int mBase = blockIdx.x * 128;
    int ntBegin = blockIdx.y * ntPerY;

    #pragma unroll
    for (int it = 0; it < 8; ++it) {
        int id = tid + it * 256;
        int r = id >> 4;
        int c = id & 15;
        uint32_t so = tile_off(r, c);
        *(uint4*)(smem + SM_AH + so) = ((const uint4*)(Ah + (size_t)(mBase + r) * CH))[c];
        *(uint4*)(smem + SM_AL + so) = ((const uint4*)(Al + (size_t)(mBase + r) * CH))[c];
    }

    for (int t = 0; t < ntPerY; ++t) {
        int nt = ntBegin + t;
        int colBase = nt * 64;
        __syncthreads();
        #pragma unroll
        for (int it = 0; it < 4; ++it) {
            int id = tid + it * 256;
            int r = id >> 4;
            int c = id & 15;
            uint32_t so = tile_off(r, c);
            *(uint4*)(smem + SM_BH + so) = ((const uint4*)(Bh + (size_t)(colBase + r) * CH))[c];
            *(uint4*)(smem + SM_BL + so) = ((const uint4*)(Bl + (size_t)(colBase + r) * CH))[c];
        }
        __syncthreads();

        float acc[2][4][4];
        #pragma unroll
        for (int a = 0; a < 2; ++a)
            #pragma unroll
            for (int b = 0; b < 4; ++b)
                #pragma unroll
                for (int c = 0; c < 4; ++c) acc[a][b][c] = 0.f;

        #pragma unroll
        for (int ks = 0; ks < 8; ++ks) {
            int c0 = ks * 2;
            uint32_t a_h[2][4], a_l[2][4], b_h[2][4], b_l[2][4];
            #pragma unroll
            for (int mb = 0; mb < 2; ++mb) {
                int row = wm * 32 + mb * 16 + (g & 1) * 8 + i8;
                int ch = c0 + (g >> 1);
                uint32_t off = tile_off(row, ch);
                ldmat_x4(a_h[mb], sb + SM_AH + off);
                ldmat_x4(a_l[mb], sb + SM_AL + off);
            }
            #pragma unroll
            for (int np = 0; np < 2; ++np) {
                int rn = wn * 32 + np * 16 + (g >> 1) * 8 + i8;
                int ch = c0 + (g & 1);
                uint32_t off = tile_off(rn, ch);
                ldmat_x4(b_h[np], sb + SM_BH + off);
                ldmat_x4(b_l[np], sb + SM_BL + off);
            }
            #pragma unroll
            for (int mb = 0; mb < 2; ++mb)
                #pragma unroll
                for (int nb = 0; nb < 4; ++nb) {
                    float* ac = acc[mb][nb];
                    const uint32_t* bh = &b_h[nb >> 1][(nb & 1) * 2];
                    const uint32_t* bl = &b_l[nb >> 1][(nb & 1) * 2];
                    mma16816(ac, a_h[mb], bh);
                    mma16816(ac, a_h[mb], bl);
                    mma16816(ac, a_l[mb], bh);
                }
        }

        #pragma unroll
        for (int mb = 0; mb < 2; ++mb) {
            int gr = mBase + wm * 32 + mb * 16 + (lane >> 2);
            #pragma unroll
            for (int nb = 0; nb < 4; ++nb) {
                int gc = colBase + wn * 32 + nb * 8 + (lane & 3) * 2;
                float* ac = acc[mb][nb];
                if (mode == 0) {
                    if (gc < P) {
                        float bx = bias ? __ldg(bias + gc) : 0.f;
                        float by = bias ? __ldg(bias + gc + 1) : 0.f;
                        if (gr < M)
                            *(float2*)(C + (size_t)gr * P + gc) =
                                make_float2(ac[0] + bx, ac[1] + by);
                        if (gr + 8 < M)
                            *(float2*)(C + (size_t)(gr + 8) * P + gc) =
                                make_float2(ac[2] + bx, ac[3] + by);
                    }
                } else {
                    #pragma unroll
                    for (int e = 0; e < 4; ++e) {
                        int c = gc + (e & 1);
                        int r = gr + (e >> 1) * 8;
                        if (c < 65 && r < M) {
                            float v = ac[e] + g_hbias[c];
                            if (c < 30)      o1[(size_t)r * 30 + c] = v;
                            else if (c < 50) o2[(size_t)r * 20 + (c - 30)] = v;
                            else             o3[(size_t)r * 15 + (c - 50)] = v;
                        }
                    }
                }
            }
        }
    }
}

// ---------------- launch ----------------
extern "C" void kernel_launch(void* const* d_in, const int* in_sizes, int n_in,
                              void* d_out, int out_size) {
    const float* x  = (const float*)d_in[0];
    const void*  ei = d_in[1];
    const float* W1 = (const float*)d_in[2];
    const float* b1 = (const float*)d_in[3];
    const float* W2 = (const float*)d_in[4];
    const float* b2 = (const float*)d_in[5];
    const float* Wt = (const float*)d_in[6];
    const float* bt = (const float*)d_in[7];
    const float* Ws = (const float*)d_in[8];
    const float* bs = (const float*)d_in[9];
    const float* Wf = (const float*)d_in[10];
    const float* bf = (const float*)d_in[11];
    const float* Wa = (const float*)d_in[12];
    const float* ba = (const float*)d_in[13];
    float* out = (float*)d_out;

    float *bufA;
    __nv_bfloat16 *Xhi, *Xlo, *Whi, *Wlo;
    cudaGetSymbolAddress((void**)&bufA, g_bufA);
    cudaGetSymbolAddress((void**)&Xhi, g_Xhi);
    cudaGetSymbolAddress((void**)&Xlo, g_Xlo);
    cudaGetSymbolAddress((void**)&Whi, g_Whi);
    cudaGetSymbolAddress((void**)&Wlo, g_Wlo);

    cudaFuncSetAttribute(k_mma_gemm, cudaFuncAttributeMaxDynamicSharedMemorySize, SM_TOTAL);

    const int T = 256;

    // ---- prep + CSR build ----
    k_detect<<<1, 1>>>((const int*)ei);
    k_prep<<<(NPAD * CH / 4 + T - 1) / T, T>>>(x, W1, W2, Wt, Ws, Wf, Wa, bt, bs, bf, ei);
    k_scan<<<1, 1024>>>();
    k_fill<<<(NE + T - 1) / T, T>>>(ei);

    // ---- layer 1 ----
    k_mma_gemm<<<dim3(MTILES, 2), 256, SM_TOTAL>>>(Xhi, Xlo, Whi, Wlo, nullptr, bufA,
                                                   NN, CH, 1, 0, nullptr, nullptr, nullptr);
    k_agg_csr<<<(NN + 7) / 8, 256>>>(bufA, b1, 1);

    // ---- layer 2 ----
    k_mma_gemm<<<dim3(MTILES, 2), 256, SM_TOTAL>>>(Xhi, Xlo,
                                                   Whi + (size_t)128 * CH, Wlo + (size_t)128 * CH,
                                                   nullptr, bufA,
                                                   NN, CH, 1, 0, nullptr, nullptr, nullptr);
    k_agg_csr<<<(NN + 7) / 8, 256>>>(bufA, b2, 0);

    // ---- small heads (type 30 | school 20 | time 15) ----
    k_mma_gemm<<<dim3(MTILES, 2), 256, SM_TOTAL>>>(Xhi, Xlo,
                                                   Whi + (size_t)256 * CH, Wlo + (size_t)256 * CH,
                                                   nullptr, nullptr,
                                                   NN, 65, 1, 1,
                                                   out, out + (size_t)NN * 30,
                                                   out + (size_t)NN * 50);

    // ---- author head P=2000 (padded 2048 -> 32 n-tiles of 64, split 4 ways) ----
    k_mma_gemm<<<dim3(MTILES, 4), 256, SM_TOTAL>>>(Xhi, Xlo,
                                                   Whi + (size_t)384 * CH, Wlo + (size_t)384 * CH,
                                                   ba, out + (size_t)NN * 65,
                                                   NN, 2000, 8, 0, nullptr, nullptr, nullptr);
}

// round 17
// speedup vs baseline: 1.4776x; 1.4776x over previous
#include <cuda_runtime.h>
#include <cuda_bf16.h>
#include <cstdint>

#define NN 50000
#define NE 800000
#define CH 128
#define NPAD 50048            // 391 * 128
#define MTILES 391
#define WROWS 2432            // W1(128) | W2(128) | heads(128) | Wa(2048)

// ---------------- scratch (no allocations allowed) ----------------
__device__ float g_dinv[NN];
__device__ int   g_cnt[NN];            // starts 0; k_scan re-zeroes after use
__device__ int   g_rowstart[NN + 1];
__device__ int   g_cursor[NN];
__device__ int   g_ecol[NE];
__device__ float g_enorm[NE];
__device__ float g_bufA[(size_t)NN * CH];
__device__ __nv_bfloat16 g_Xhi[(size_t)NPAD * CH];
__device__ __nv_bfloat16 g_Xlo[(size_t)NPAD * CH];
__device__ __nv_bfloat16 g_Whi[(size_t)WROWS * CH];
__device__ __nv_bfloat16 g_Wlo[(size_t)WROWS * CH];
__device__ float g_hbias[65];
__device__ int   g_is64;

// ================= helpers =================
__device__ __forceinline__ uint32_t smem_u32(const void* p) {
    uint32_t a;
    asm("{ .reg .u64 t; cvta.to.shared.u64 t, %1; cvt.u32.u64 %0, t; }" : "=r"(a) : "l"(p));
    return a;
}
__device__ __forceinline__ void ldmat_x4(uint32_t* r, uint32_t addr) {
    asm volatile("ldmatrix.sync.aligned.m8n8.x4.shared.b16 {%0,%1,%2,%3}, [%4];"
        : "=r"(r[0]), "=r"(r[1]), "=r"(r[2]), "=r"(r[3]) : "r"(addr));
}
__device__ __forceinline__ void mma16816(float* d, const uint32_t* a, const uint32_t* b) {
    asm volatile("mma.sync.aligned.m16n8k16.row.col.f32.bf16.bf16.f32 "
        "{%0,%1,%2,%3}, {%4,%5,%6,%7}, {%8,%9}, {%0,%1,%2,%3};"
        : "+f"(d[0]), "+f"(d[1]), "+f"(d[2]), "+f"(d[3])
        : "r"(a[0]), "r"(a[1]), "r"(a[2]), "r"(a[3]), "r"(b[0]), "r"(b[1]));
}
__device__ __forceinline__ void split_store(float v, __nv_bfloat16* hi, __nv_bfloat16* lo) {
    __nv_bfloat16 h = __float2bfloat16(v);
    *hi = h;
    *lo = __float2bfloat16(v - __bfloat162float(h));
}

// ---------------- edge-index dtype sniff ----------------
__global__ void k_detect(const int* __restrict__ ei32) {
    int z = 0;
    for (int i = 1; i < 256; i += 2)
        if (ei32[i] == 0) z++;
    g_is64 = (z > 64) ? 1 : 0;
}
__device__ __forceinline__ int edge_at(const void* __restrict__ ei, int pos) {
    if (g_is64) return (int)((const long long*)ei)[pos];
    return ((const int*)ei)[pos];
}

// ---------------- fused prep: feat split | weight split | degree count | bias pack ----
__global__ void k_prep(const float* __restrict__ x,
                       const float* __restrict__ W1, const float* __restrict__ W2,
                       const float* __restrict__ Wt, const float* __restrict__ Ws,
                       const float* __restrict__ Wf, const float* __restrict__ Wa,
                       const float* __restrict__ bt, const float* __restrict__ bs,
                       const float* __restrict__ bf, const void* __restrict__ ei) {
    int id = blockIdx.x * blockDim.x + threadIdx.x;

    // --- task 1: feature fp32 -> bf16 hi/lo (incl. zero pad rows) ---
    if (id < NPAD * CH / 4) {
        int row = id >> 5;
        float4 v = make_float4(0.f, 0.f, 0.f, 0.f);
        if (row < NN) v = ((const float4*)x)[id];
        __nv_bfloat16 h0 = __float2bfloat16(v.x), h1 = __float2bfloat16(v.y);
        __nv_bfloat16 h2 = __float2bfloat16(v.z), h3 = __float2bfloat16(v.w);
        __nv_bfloat162 hA(h0, h1), hB(h2, h3);
        __nv_bfloat162 lA(__float2bfloat16(v.x - __bfloat162float(h0)),
                          __float2bfloat16(v.y - __bfloat162float(h1)));
        __nv_bfloat162 lB(__float2bfloat16(v.z - __bfloat162float(h2)),
                          __float2bfloat16(v.w - __bfloat162float(h3)));
        ((__nv_bfloat162*)g_Xhi)[id * 2] = hA;
        ((__nv_bfloat162*)g_Xhi)[id * 2 + 1] = hB;
        ((__nv_bfloat162*)g_Xlo)[id * 2] = lA;
        ((__nv_bfloat162*)g_Xlo)[id * 2 + 1] = lB;
    }

    // --- task 2: all weights -> transposed [WROWS x 128] hi/lo ---
    if (id < WROWS * CH) {
        int n = id >> 7, k = id & 127;
        float v = 0.f;
        if (n < 128)       v = W1[(size_t)k * 128 + n];
        else if (n < 256)  v = W2[(size_t)k * 128 + (n - 128)];
        else if (n < 384) {
            int m = n - 256;
            if (m < 30)      v = Wt[(size_t)k * 30 + m];
            else if (m < 50) v = Ws[(size_t)k * 20 + (m - 30)];
            else if (m < 65) v = Wf[(size_t)k * 15 + (m - 50)];
        } else {
            int m = n - 384;
            if (m < 2000) v = Wa[(size_t)k * 2000 + m];
        }
        split_store(v, &g_Whi[id], &g_Wlo[id]);
    }

    // --- task 3: degree count ---
    if (id < NE) atomicAdd(&g_cnt[edge_at(ei, id)], 1);

    // --- task 4: packed small-head bias ---
    if (id < 30)      g_hbias[id] = bt[id];
    else if (id < 50) g_hbias[id] = bs[id - 30];
    else if (id < 65) g_hbias[id] = bf[id - 50];
}

// ---------------- scan (+dinv, +cnt clear) ----------------
__global__ void k_scan() {
    __shared__ int swarp[32];
    __shared__ int s_carry;
    int tid = threadIdx.x, lane = tid & 31, wid = tid >> 5;
    if (tid == 0) s_carry = 0;
    __syncthreads();
    for (int base = 0; base < NN; base += 1024) {
        int i = base + tid;
        int v = 0;
        if (i < NN) {
            v = g_cnt[i];
            g_dinv[i] = rsqrtf((float)(v + 1));
            g_cnt[i] = 0;
        }
        int incl = v;
        #pragma unroll
        for (int d = 1; d < 32; d <<= 1) {
            int n = __shfl_up_sync(0xffffffffu, incl, d);
            if (lane >= d) incl += n;
        }
        if (lane == 31) swarp[wid] = incl;
        __syncthreads();
        if (wid == 0) {
            int wv = swarp[lane];
            int wincl = wv;
            #pragma unroll
            for (int d = 1; d < 32; d <<= 1) {
                int n = __shfl_up_sync(0xffffffffu, wincl, d);
                if (lane >= d) wincl += n;
            }
            swarp[lane] = wincl - wv;
        }
        __syncthreads();
        int excl = s_carry + swarp[wid] + incl - v;
        if (i < NN) { g_rowstart[i] = excl; g_cursor[i] = excl; }
        __syncthreads();
        if (tid == 1023) s_carry = excl + v;
        __syncthreads();
    }
    if (threadIdx.x == 0) g_rowstart[NN] = s_carry;
}

__global__ void k_fill(const void* __restrict__ ei) {
    int e = blockIdx.x * blockDim.x + threadIdx.x;
    if (e >= NE) return;
    int r = edge_at(ei, e);
    int c = edge_at(ei, NE + e);
    int pos = atomicAdd(&g_cursor[r], 1);
    g_ecol[pos] = c;
    g_enorm[pos] = g_dinv[r] * g_dinv[c];
}

// ---------------- CSR gather aggregation (fused: self + bias + relu + bf16 split) ----
__global__ __launch_bounds__(256) void k_agg_csr(const float* __restrict__ hin,
                                                 const float* __restrict__ bias, int relu) {
    int node = blockIdx.x * 8 + (threadIdx.x >> 5);
    if (node >= NN) return;
    int lane = threadIdx.x & 31;
    float d = g_dinv[node];
    float dd = d * d;
    float4 acc = ((const float4*)(hin + (size_t)node * CH))[lane];
    acc.x *= dd; acc.y *= dd; acc.z *= dd; acc.w *= dd;

    int s = g_rowstart[node], e = g_rowstart[node + 1];
    int j = s;
    for (; j + 4 <= e; j += 4) {
        int   c0 = g_ecol[j],     c1 = g_ecol[j + 1];
        int   c2 = g_ecol[j + 2], c3 = g_ecol[j + 3];
        float w0 = g_enorm[j],    w1 = g_enorm[j + 1];
        float w2 = g_enorm[j + 2], w3 = g_enorm[j + 3];
        float4 v0 = ((const float4*)(hin + (size_t)c0 * CH))[lane];
        float4 v1 = ((const float4*)(hin + (size_t)c1 * CH))[lane];
        float4 v2 = ((const float4*)(hin + (size_t)c2 * CH))[lane];
        float4 v3 = ((const float4*)(hin + (size_t)c3 * CH))[lane];
        acc.x += v0.x * w0 + v1.x * w1 + v2.x * w2 + v3.x * w3;
        acc.y += v0.y * w0 + v1.y * w1 + v2.y * w2 + v3.y * w3;
        acc.z += v0.z * w0 + v1.z * w1 + v2.z * w2 + v3.z * w3;
        acc.w += v0.w * w0 + v1.w * w1 + v2.w * w2 + v3.w * w3;
    }
    for (; j < e; ++j) {
        int c0 = g_ecol[j];
        float w0 = g_enorm[j];
        float4 v0 = ((const float4*)(hin + (size_t)c0 * CH))[lane];
        acc.x += v0.x * w0; acc.y += v0.y * w0;
        acc.z += v0.z * w0; acc.w += v0.w * w0;
    }

    float4 b = ((const float4*)bias)[lane];
    acc.x += b.x; acc.y += b.y; acc.z += b.z; acc.w += b.w;
    if (relu) {
        acc.x = fmaxf(acc.x, 0.f); acc.y = fmaxf(acc.y, 0.f);
        acc.z = fmaxf(acc.z, 0.f); acc.w = fmaxf(acc.w, 0.f);
    }
    __nv_bfloat16 h0 = __float2bfloat16(acc.x), h1 = __float2bfloat16(acc.y);
    __nv_bfloat16 h2 = __float2bfloat16(acc.z), h3 = __float2bfloat16(acc.w);
    __nv_bfloat162 hA(h0, h1), hB(h2, h3);
    __nv_bfloat162 lA(__float2bfloat16(acc.x - __bfloat162float(h0)),
                      __float2bfloat16(acc.y - __bfloat162float(h1)));
    __nv_bfloat162 lB(__float2bfloat16(acc.z - __bfloat162float(h2)),
                      __float2bfloat16(acc.w - __bfloat162float(h3)));
    size_t o = (size_t)node * 64 + lane * 2;
    ((__nv_bfloat162*)g_Xhi)[o]     = hA;
    ((__nv_bfloat162*)g_Xhi)[o + 1] = hB;
    ((__nv_bfloat162*)g_Xlo)[o]     = lA;
    ((__nv_bfloat162*)g_Xlo)[o + 1] = lB;
}

// ---------------- mma.sync bf16-split GEMM (Round-13 config: occ 2) ----------------
// C[M x P] = A[M x 128] @ W[128 x P] (+bias), A/W pre-split into bf16 hi/lo.
// BM=128, BN=64, K=128 fully staged. 256 threads = 8 warps, warp tile 32x32.
#define SM_AH 0
#define SM_AL 32768
#define SM_BH 65536
#define SM_BL (65536 + 16384)
#define SM_TOTAL (65536 + 32768)

__device__ __forceinline__ uint32_t tile_off(int row, int chunk) {
    return (uint32_t)row * 256u + (uint32_t)((chunk ^ (row & 7)) << 4);
}

__global__ __launch_bounds__(256, 2) void k_mma_gemm(
    const __nv_bfloat16* __restrict__ Ah, const __nv_bfloat16* __restrict__ Al,
    const __nv_bfloat16* __restrict__ Bh, const __nv_bfloat16* __restrict__ Bl,
    const float* __restrict__ bias, float* __restrict__ C,
    int M, int P, int ntPerY, int mode,
    float* __restrict__ o1, float* __restrict__ o2, float* __restrict__ o3)
{
    extern __shared__ __align__(1024) char smem[];
    uint32_t sb = smem_u32(smem);
    int tid = threadIdx.x;
    int lane = tid & 31;
    int wid = tid >> 5;
    int wm = wid & 3;
    int wn = wid >> 2;
    int g = lane >> 3, i8 = lane & 7;
    int mBase = blockIdx.x * 128;
    int ntBegin = blockIdx.y * ntPerY;

    #pragma unroll
    for (int it = 0; it < 8; ++it) {
        int id = tid + it * 256;
        int r = id >> 4;
        int c = id & 15;
        uint32_t so = tile_off(r, c);
        *(uint4*)(smem + SM_AH + so) = ((const uint4*)(Ah + (size_t)(mBase + r) * CH))[c];
        *(uint4*)(smem + SM_AL + so) = ((const uint4*)(Al + (size_t)(mBase + r) * CH))[c];
    }

    for (int t = 0; t < ntPerY; ++t) {
        int nt = ntBegin + t;
        int colBase = nt * 64;
        __syncthreads();
        #pragma unroll
        for (int it = 0; it < 4; ++it) {
            int id = tid + it * 256;
            int r = id >> 4;
            int c = id & 15;
            uint32_t so = tile_off(r, c);
            *(uint4*)(smem + SM_BH + so) = ((const uint4*)(Bh + (size_t)(colBase + r) * CH))[c];
            *(uint4*)(smem + SM_BL + so) = ((const uint4*)(Bl + (size_t)(colBase + r) * CH))[c];
        }
        __syncthreads();

        float acc[2][4][4];
        #pragma unroll
        for (int a = 0; a < 2; ++a)
            #pragma unroll
            for (int b = 0; b < 4; ++b)
                #pragma unroll
                for (int c = 0; c < 4; ++c) acc[a][b][c] = 0.f;

        #pragma unroll
        for (int ks = 0; ks < 8; ++ks) {
            int c0 = ks * 2;
            uint32_t a_h[2][4], a_l[2][4], b_h[2][4], b_l[2][4];
            #pragma unroll
            for (int mb = 0; mb < 2; ++mb) {
                int row = wm * 32 + mb * 16 + (g & 1) * 8 + i8;
                int ch = c0 + (g >> 1);
                uint32_t off = tile_off(row, ch);
                ldmat_x4(a_h[mb], sb + SM_AH + off);
                ldmat_x4(a_l[mb], sb + SM_AL + off);
            }
            #pragma unroll
            for (int np = 0; np < 2; ++np) {
                int rn = wn * 32 + np * 16 + (g >> 1) * 8 + i8;
                int ch = c0 + (g & 1);
                uint32_t off = tile_off(rn, ch);
                ldmat_x4(b_h[np], sb + SM_BH + off);
                ldmat_x4(b_l[np], sb + SM_BL + off);
            }
            #pragma unroll
            for (int mb = 0; mb < 2; ++mb)
                #pragma unroll
                for (int nb = 0; nb < 4; ++nb) {
                    float* ac = acc[mb][nb];
                    const uint32_t* bh = &b_h[nb >> 1][(nb & 1) * 2];
                    const uint32_t* bl = &b_l[nb >> 1][(nb & 1) * 2];
                    mma16816(ac, a_h[mb], bh);
                    mma16816(ac, a_h[mb], bl);
                    mma16816(ac, a_l[mb], bh);
                }
        }

        #pragma unroll
        for (int mb = 0; mb < 2; ++mb) {
            int gr = mBase + wm * 32 + mb * 16 + (lane >> 2);
            #pragma unroll
            for (int nb = 0; nb < 4; ++nb) {
                int gc = colBase + wn * 32 + nb * 8 + (lane & 3) * 2;
                float* ac = acc[mb][nb];
                if (mode == 0) {
                    if (gc < P) {
                        float bx = bias ? __ldg(bias + gc) : 0.f;
                        float by = bias ? __ldg(bias + gc + 1) : 0.f;
                        if (gr < M)
                            *(float2*)(C + (size_t)gr * P + gc) =
                                make_float2(ac[0] + bx, ac[1] + by);
                        if (gr + 8 < M)
                            *(float2*)(C + (size_t)(gr + 8) * P + gc) =
                                make_float2(ac[2] + bx, ac[3] + by);
                    }
                } else {
                    #pragma unroll
                    for (int e = 0; e < 4; ++e) {
                        int c = gc + (e & 1);
                        int r = gr + (e >> 1) * 8;
                        if (c < 65 && r < M) {
                            float v = ac[e] + g_hbias[c];
                            if (c < 30)      o1[(size_t)r * 30 + c] = v;
                            else if (c < 50) o2[(size_t)r * 20 + (c - 30)] = v;
                            else             o3[(size_t)r * 15 + (c - 50)] = v;
                        }
                    }
                }
            }
        }
    }
}

// ---------------- launch ----------------
extern "C" void kernel_launch(void* const* d_in, const int* in_sizes, int n_in,
                              void* d_out, int out_size) {
    const float* x  = (const float*)d_in[0];
    const void*  ei = d_in[1];
    const float* W1 = (const float*)d_in[2];
    const float* b1 = (const float*)d_in[3];
    const float* W2 = (const float*)d_in[4];
    const float* b2 = (const float*)d_in[5];
    const float* Wt = (const float*)d_in[6];
    const float* bt = (const float*)d_in[7];
    const float* Ws = (const float*)d_in[8];
    const float* bs = (const float*)d_in[9];
    const float* Wf = (const float*)d_in[10];
    const float* bf = (const float*)d_in[11];
    const float* Wa = (const float*)d_in[12];
    const float* ba = (const float*)d_in[13];
    float* out = (float*)d_out;

    float *bufA;
    __nv_bfloat16 *Xhi, *Xlo, *Whi, *Wlo;
    cudaGetSymbolAddress((void**)&bufA, g_bufA);
    cudaGetSymbolAddress((void**)&Xhi, g_Xhi);
    cudaGetSymbolAddress((void**)&Xlo, g_Xlo);
    cudaGetSymbolAddress((void**)&Whi, g_Whi);
    cudaGetSymbolAddress((void**)&Wlo, g_Wlo);

    cudaFuncSetAttribute(k_mma_gemm, cudaFuncAttributeMaxDynamicSharedMemorySize, SM_TOTAL);

    const int T = 256;

    // ---- prep + CSR build ----
    k_detect<<<1, 1>>>((const int*)ei);
    k_prep<<<(NPAD * CH / 4 + T - 1) / T, T>>>(x, W1, W2, Wt, Ws, Wf, Wa, bt, bs, bf, ei);
    k_scan<<<1, 1024>>>();
    k_fill<<<(NE + T - 1) / T, T>>>(ei);

    // ---- layer 1 ----
    k_mma_gemm<<<dim3(MTILES, 2), 256, SM_TOTAL>>>(Xhi, Xlo, Whi, Wlo, nullptr, bufA,
                                                   NN, CH, 1, 0, nullptr, nullptr, nullptr);
    k_agg_csr<<<(NN + 7) / 8, 256>>>(bufA, b1, 1);

    // ---- layer 2 ----
    k_mma_gemm<<<dim3(MTILES, 2), 256, SM_TOTAL>>>(Xhi, Xlo,
                                                   Whi + (size_t)128 * CH, Wlo + (size_t)128 * CH,
                                                   nullptr, bufA,
                                                   NN, CH, 1, 0, nullptr, nullptr, nullptr);
    k_agg_csr<<<(NN + 7) / 8, 256>>>(bufA, b2, 0);

    // ---- small heads (type 30 | school 20 | time 15) ----
    k_mma_gemm<<<dim3(MTILES, 2), 256, SM_TOTAL>>>(Xhi, Xlo,
                                                   Whi + (size_t)256 * CH, Wlo + (size_t)256 * CH,
                                                   nullptr, nullptr,
                                                   NN, 65, 1, 1,
                                                   out, out + (size_t)NN * 30,
                                                   out + (size_t)NN * 50);

    // ---- author head P=2000 (padded 2048 -> 32 n-tiles of 64, split 2 ways) ----
    k_mma_gemm<<<dim3(MTILES, 2), 256, SM_TOTAL>>>(Xhi, Xlo,
                                                   Whi + (size_t)384 * CH, Wlo + (size_t)384 * CH,
                                                   ba, out + (size_t)NN * 65,
                                                   NN, 2000, 16, 0, nullptr, nullptr, nullptr);
}